// round 1
// baseline (speedup 1.0000x reference)
#include <cuda_runtime.h>

// Problem constants
constexpr int Bn = 4;
constexpr int Sn = 4096;
constexpr int Dn = 64;
constexpr int Hn = 16;
constexpr int BHn = Bn * Hn;        // 64
constexpr int NSPLIT = 8;
constexpr int SCHUNK = Sn / NSPLIT; // 512
constexpr int CH = 32;              // s-rows staged per smem chunk
constexpr int PAD = 68;             // padded row stride (floats), 16B-aligned, bank-spread
constexpr float PIC = 3.1415f;      // verbatim constant from reference

// Static device scratch (allowed; no runtime allocation)
__device__ float g_partKV [NSPLIT * BHn * Dn * Dn];
__device__ float g_partKVp[NSPLIT * BHn * Dn * Dn];
__device__ float g_partKs [NSPLIT * BHn * Dn];
__device__ float g_partKps[NSPLIT * BHn * Dn];
__device__ float g_M  [BHn * Dn * Dn];
__device__ float g_Mp [BHn * Dn * Dn];
__device__ float g_Ksum [BHn * Dn];
__device__ float g_Kpsum[BHn * Dn];

// elu(x)+1 :  x>0 ? x+1 : exp(x)
__device__ __forceinline__ float elu1(float v) {
    return (v > 0.f) ? (v + 1.f) : __expf(v);
}

// ---------------------------------------------------------------------------
// Kernel 1: per (b,h,split) fused K/V head-projection + rank-1 KV reduction.
// Produces deterministic per-split partials of KV, KVp (=sin-weighted), Ksum, Kpsum.
// ---------------------------------------------------------------------------
__global__ __launch_bounds__(256)
void kv_kernel(const float* __restrict__ key, const float* __restrict__ value,
               const float* __restrict__ wk_w, const float* __restrict__ wk_b,
               const float* __restrict__ wv_w, const float* __restrict__ wv_b)
{
    extern __shared__ float sm[];
    float* sWk   = sm;                  // 64*64
    float* sWv   = sWk + 4096;          // 64*64
    float* sRawK = sWv + 4096;          // CH*PAD
    float* sRawV = sRawK + CH * PAD;    // CH*PAD
    float* sKp   = sRawV + CH * PAD;    // CH*PAD
    float* sVp   = sKp  + CH * PAD;     // CH*PAD
    float* sSin  = sVp  + CH * PAD;     // CH

    const int bh    = blockIdx.x;
    const int split = blockIdx.y;
    const int b     = bh >> 4;
    const int h     = bh & 15;
    const int tid   = threadIdx.x;

    // head weight slices -> smem
    for (int i = tid; i < 4096; i += 256) {
        int k = i >> 6, c = i & 63;
        sWk[i] = wk_w[k * 1024 + h * 64 + c];
        sWv[i] = wv_w[k * 1024 + h * 64 + c];
    }

    const int x  = tid >> 2;          // KV row owned (0..63)
    const int z0 = (tid & 3) * 16;    // KV col group (16 cols)
    const int pr = tid >> 3;          // projection row (0..31)
    const int pc = (tid & 7) * 8;     // projection col group (8 cols)

    float bk[8], bv[8];
    #pragma unroll
    for (int j = 0; j < 8; j++) {
        bk[j] = wk_b[h * 64 + pc + j];
        bv[j] = wv_b[h * 64 + pc + j];
    }

    float accKV[16], accKVp[16];
    #pragma unroll
    for (int j = 0; j < 16; j++) { accKV[j] = 0.f; accKVp[j] = 0.f; }
    float sk = 0.f, skp = 0.f;

    __syncthreads();

    const int sbase = split * SCHUNK;
    for (int sc = 0; sc < SCHUNK; sc += CH) {
        // stage raw k,v rows
        for (int i = tid; i < CH * 64; i += 256) {
            int r = i >> 6, d = i & 63;
            size_t g = ((size_t)(b * Sn + sbase + sc + r)) * 64 + d;
            sRawK[r * PAD + d] = key[g];
            sRawV[r * PAD + d] = value[g];
        }
        if (tid < CH) {
            int sg = sbase + sc + tid;
            sSin[tid] = sinf((PIC * (float)sg) / (float)Sn);
        }
        __syncthreads();

        // project: kp = elu(rawK @ Wk_h + bk)+1 ; vp = rawV @ Wv_h + bv
        {
            float ak[8], av[8];
            #pragma unroll
            for (int j = 0; j < 8; j++) { ak[j] = bk[j]; av[j] = bv[j]; }
            #pragma unroll 8
            for (int kk = 0; kk < 64; kk++) {
                float a  = sRawK[pr * PAD + kk];
                float a2 = sRawV[pr * PAD + kk];
                const float4* wk4 = reinterpret_cast<const float4*>(&sWk[kk * 64 + pc]);
                const float4* wv4 = reinterpret_cast<const float4*>(&sWv[kk * 64 + pc]);
                float4 w0 = wk4[0], w1 = wk4[1];
                float4 u0 = wv4[0], u1 = wv4[1];
                ak[0] += a * w0.x; ak[1] += a * w0.y; ak[2] += a * w0.z; ak[3] += a * w0.w;
                ak[4] += a * w1.x; ak[5] += a * w1.y; ak[6] += a * w1.z; ak[7] += a * w1.w;
                av[0] += a2 * u0.x; av[1] += a2 * u0.y; av[2] += a2 * u0.z; av[3] += a2 * u0.w;
                av[4] += a2 * u1.x; av[5] += a2 * u1.y; av[6] += a2 * u1.z; av[7] += a2 * u1.w;
            }
            #pragma unroll
            for (int j = 0; j < 8; j++) {
                sKp[pr * PAD + pc + j] = elu1(ak[j]);
                sVp[pr * PAD + pc + j] = av[j];
            }
        }
        __syncthreads();

        // rank-1 accumulation into register tiles
        #pragma unroll 4
        for (int ss = 0; ss < CH; ss++) {
            float kx  = sKp[ss * PAD + x];
            float sw  = sSin[ss];
            float kxp = kx * sw;
            sk += kx; skp += kxp;
            const float4* vp4 = reinterpret_cast<const float4*>(&sVp[ss * PAD + z0]);
            float4 v0 = vp4[0], v1 = vp4[1], v2 = vp4[2], v3 = vp4[3];
            float vb[16] = { v0.x, v0.y, v0.z, v0.w,  v1.x, v1.y, v1.z, v1.w,
                             v2.x, v2.y, v2.z, v2.w,  v3.x, v3.y, v3.z, v3.w };
            #pragma unroll
            for (int j = 0; j < 16; j++) {
                accKV[j]  += kx  * vb[j];
                accKVp[j] += kxp * vb[j];
            }
        }
        __syncthreads();
    }

    size_t base = ((size_t)(split * BHn + bh)) * Dn * Dn + x * 64 + z0;
    #pragma unroll
    for (int j = 0; j < 16; j += 4) {
        *reinterpret_cast<float4*>(&g_partKV [base + j]) =
            make_float4(accKV[j], accKV[j+1], accKV[j+2], accKV[j+3]);
        *reinterpret_cast<float4*>(&g_partKVp[base + j]) =
            make_float4(accKVp[j], accKVp[j+1], accKVp[j+2], accKVp[j+3]);
    }
    if ((tid & 3) == 0) {
        int vb = (split * BHn + bh) * 64 + x;
        g_partKs [vb] = sk;
        g_partKps[vb] = skp;
    }
}

// ---------------------------------------------------------------------------
// Kernel 2: reduce split partials (fixed order -> deterministic), fold dense:
//           M = KV @ Wd_h,  Mp = KVp @ Wd_h ; also finalize Ksum/Kpsum.
// ---------------------------------------------------------------------------
__global__ __launch_bounds__(256)
void mprep_kernel(const float* __restrict__ dense_w)
{
    extern __shared__ float sm[];
    float* sKV  = sm;                // 64*PAD
    float* sKVp = sKV + 64 * PAD;    // 64*PAD
    float* sWd  = sKVp + 64 * PAD;   // 64*64

    const int bh  = blockIdx.x;
    const int h   = bh & 15;
    const int tid = threadIdx.x;
    const int x   = tid >> 2;
    const int z0  = (tid & 3) * 16;

    float r0[16], r1[16];
    #pragma unroll
    for (int j = 0; j < 16; j++) { r0[j] = 0.f; r1[j] = 0.f; }
    for (int sp = 0; sp < NSPLIT; sp++) {
        size_t base = ((size_t)(sp * BHn + bh)) * Dn * Dn + x * 64 + z0;
        #pragma unroll
        for (int j = 0; j < 16; j += 4) {
            float4 a = *reinterpret_cast<const float4*>(&g_partKV [base + j]);
            float4 c = *reinterpret_cast<const float4*>(&g_partKVp[base + j]);
            r0[j] += a.x; r0[j+1] += a.y; r0[j+2] += a.z; r0[j+3] += a.w;
            r1[j] += c.x; r1[j+1] += c.y; r1[j+2] += c.z; r1[j+3] += c.w;
        }
    }
    #pragma unroll
    for (int j = 0; j < 16; j++) {
        sKV [x * PAD + z0 + j] = r0[j];
        sKVp[x * PAD + z0 + j] = r1[j];
    }
    if (tid < 64) {
        float a = 0.f, c = 0.f;
        for (int sp = 0; sp < NSPLIT; sp++) {
            a += g_partKs [(sp * BHn + bh) * 64 + tid];
            c += g_partKps[(sp * BHn + bh) * 64 + tid];
        }
        g_Ksum [bh * 64 + tid] = a;
        g_Kpsum[bh * 64 + tid] = c;
    }
    for (int i = tid; i < 4096; i += 256) {
        int r = i >> 6, c = i & 63;
        sWd[i] = dense_w[(h * 64 + r) * 64 + c];
    }
    __syncthreads();

    float m0[16], m1[16];
    #pragma unroll
    for (int j = 0; j < 16; j++) { m0[j] = 0.f; m1[j] = 0.f; }
    #pragma unroll 8
    for (int i = 0; i < 64; i++) {
        float a  = sKV [x * PAD + i];
        float ap = sKVp[x * PAD + i];
        const float4* w4 = reinterpret_cast<const float4*>(&sWd[i * 64 + z0]);
        float4 w0 = w4[0], w1 = w4[1], w2 = w4[2], w3 = w4[3];
        float wb[16] = { w0.x, w0.y, w0.z, w0.w,  w1.x, w1.y, w1.z, w1.w,
                         w2.x, w2.y, w2.z, w2.w,  w3.x, w3.y, w3.z, w3.w };
        #pragma unroll
        for (int j = 0; j < 16; j++) {
            m0[j] += a  * wb[j];
            m1[j] += ap * wb[j];
        }
    }
    size_t ob = (size_t)bh * Dn * Dn + x * 64 + z0;
    #pragma unroll
    for (int j = 0; j < 16; j += 4) {
        *reinterpret_cast<float4*>(&g_M [ob + j]) = make_float4(m0[j], m0[j+1], m0[j+2], m0[j+3]);
        *reinterpret_cast<float4*>(&g_Mp[ob + j]) = make_float4(m1[j], m1[j+1], m1[j+2], m1[j+3]);
    }
}

// ---------------------------------------------------------------------------
// Kernel 3: fused Q head-projection + denom + output, per (b, 64-row s tile).
// out[b,s] = dense_b + sum_h den_sh * q_sh @ (M_h + w_s*Mp_h)
// ---------------------------------------------------------------------------
__global__ __launch_bounds__(256)
void out_kernel(const float* __restrict__ query,
                const float* __restrict__ wq_w, const float* __restrict__ wq_b,
                const float* __restrict__ dense_b, float* __restrict__ out)
{
    extern __shared__ float sm[];
    float* sRawQ = sm;                 // 64*PAD
    float* sQ    = sRawQ + 64 * PAD;   // 64*PAD
    float* sWq   = sQ    + 64 * PAD;   // 64*64
    float* sM    = sWq   + 4096;       // 64*PAD
    float* sMp   = sM    + 64 * PAD;   // 64*PAD
    float* sWs   = sMp   + 64 * PAD;   // 64
    float* sKs   = sWs + 64;           // 64
    float* sKps  = sKs + 64;           // 64

    const int b    = blockIdx.y;
    const int s0   = blockIdx.x * 64;
    const int tid  = threadIdx.x;
    const int srow = tid >> 2;          // s row within tile (0..63)
    const int c0   = (tid & 3) * 16;    // 16 output cols

    for (int i = tid; i < 4096; i += 256) {
        int r = i >> 6, d = i & 63;
        sRawQ[r * PAD + d] = query[((size_t)(b * Sn + s0 + r)) * 64 + d];
    }
    if (tid < 64) {
        float ps = (PIC * (float)(s0 + tid)) / (float)Sn;
        sWs[tid] = cosf(ps) + sinf(ps);
    }

    float accO[16];
    #pragma unroll
    for (int j = 0; j < 16; j++) accO[j] = 0.f;

    __syncthreads();
    const float w = sWs[srow];

    for (int h = 0; h < Hn; h++) {
        const int bh = b * 16 + h;
        for (int i = tid; i < 4096; i += 256) {
            int k = i >> 6, c = i & 63;
            sWq[i] = wq_w[k * 1024 + h * 64 + c];
        }
        for (int i = tid; i < 4096; i += 256) {
            int r = i >> 6, c = i & 63;
            sM [r * PAD + c] = g_M [(size_t)bh * 4096 + i];
            sMp[r * PAD + c] = g_Mp[(size_t)bh * 4096 + i];
        }
        if (tid < 64)                sKs [tid]      = g_Ksum [bh * 64 + tid];
        else if (tid < 128)          sKps[tid - 64] = g_Kpsum[bh * 64 + tid - 64];
        __syncthreads();

        // q projection for this head (+ elu + 1)
        {
            float acc[16];
            #pragma unroll
            for (int j = 0; j < 16; j++) acc[j] = wq_b[h * 64 + c0 + j];
            #pragma unroll 8
            for (int kk = 0; kk < 64; kk++) {
                float a = sRawQ[srow * PAD + kk];
                const float4* w4 = reinterpret_cast<const float4*>(&sWq[kk * 64 + c0]);
                float4 w0 = w4[0], w1 = w4[1], w2 = w4[2], w3 = w4[3];
                float wb[16] = { w0.x, w0.y, w0.z, w0.w,  w1.x, w1.y, w1.z, w1.w,
                                 w2.x, w2.y, w2.z, w2.w,  w3.x, w3.y, w3.z, w3.w };
                #pragma unroll
                for (int j = 0; j < 16; j++) acc[j] += a * wb[j];
            }
            #pragma unroll
            for (int j = 0; j < 16; j++)
                sQ[srow * PAD + c0 + j] = elu1(acc[j]);
        }
        __syncthreads();

        // denominator (duplicated x4 per s-row; cheap)
        float d0 = 0.f, d1 = 0.f;
        #pragma unroll
        for (int i = 0; i < 64; i += 4) {
            float4 q4 = *reinterpret_cast<const float4*>(&sQ[srow * PAD + i]);
            float4 a4 = *reinterpret_cast<const float4*>(&sKs[i]);
            float4 c4 = *reinterpret_cast<const float4*>(&sKps[i]);
            d0 += q4.x * a4.x + q4.y * a4.y + q4.z * a4.z + q4.w * a4.w;
            d1 += q4.x * c4.x + q4.y * c4.y + q4.z * c4.z + q4.w * c4.w;
        }
        float den = 1.0f / (d0 + w * d1 + 1e-5f);

        // o = q @ (M + w*Mp)
        float ot[16];
        #pragma unroll
        for (int j = 0; j < 16; j++) ot[j] = 0.f;
        #pragma unroll 4
        for (int xx = 0; xx < 64; xx++) {
            float qa = sQ[srow * PAD + xx];
            float qb = qa * w;
            const float4* m4  = reinterpret_cast<const float4*>(&sM [xx * PAD + c0]);
            const float4* mp4 = reinterpret_cast<const float4*>(&sMp[xx * PAD + c0]);
            float4 a0 = m4[0],  a1 = m4[1],  a2 = m4[2],  a3 = m4[3];
            float4 p0 = mp4[0], p1 = mp4[1], p2 = mp4[2], p3 = mp4[3];
            float mb[16]  = { a0.x, a0.y, a0.z, a0.w,  a1.x, a1.y, a1.z, a1.w,
                              a2.x, a2.y, a2.z, a2.w,  a3.x, a3.y, a3.z, a3.w };
            float mpb[16] = { p0.x, p0.y, p0.z, p0.w,  p1.x, p1.y, p1.z, p1.w,
                              p2.x, p2.y, p2.z, p2.w,  p3.x, p3.y, p3.z, p3.w };
            #pragma unroll
            for (int j = 0; j < 16; j++) ot[j] += qa * mb[j] + qb * mpb[j];
        }
        #pragma unroll
        for (int j = 0; j < 16; j++) accO[j] += den * ot[j];
        __syncthreads();
    }

    // epilogue: + dense_b, write
    size_t ob = ((size_t)(b * Sn + s0 + srow)) * 64 + c0;
    #pragma unroll
    for (int j = 0; j < 16; j += 4) {
        float4 r;
        r.x = accO[j]   + dense_b[c0 + j];
        r.y = accO[j+1] + dense_b[c0 + j + 1];
        r.z = accO[j+2] + dense_b[c0 + j + 2];
        r.w = accO[j+3] + dense_b[c0 + j + 3];
        *reinterpret_cast<float4*>(&out[ob + j]) = r;
    }
}

// ---------------------------------------------------------------------------
extern "C" void kernel_launch(void* const* d_in, const int* in_sizes, int n_in,
                              void* d_out, int out_size)
{
    const float* query   = (const float*)d_in[0];
    const float* key     = (const float*)d_in[1];
    const float* value   = (const float*)d_in[2];
    // d_in[3] = attn_mask (unused by the reference math)
    const float* wq_w    = (const float*)d_in[4];
    const float* wq_b    = (const float*)d_in[5];
    const float* wk_w    = (const float*)d_in[6];
    const float* wk_b    = (const float*)d_in[7];
    const float* wv_w    = (const float*)d_in[8];
    const float* wv_b    = (const float*)d_in[9];
    const float* dense_w = (const float*)d_in[10];
    const float* dense_b = (const float*)d_in[11];
    float* out = (float*)d_out;

    constexpr int SM_B = (4096 * 2 + CH * PAD * 4 + CH) * 4;           // ~67.7 KB
    constexpr int SM_C = (64 * PAD * 2 + 4096) * 4;                    // ~51.2 KB
    constexpr int SM_D = (64 * PAD * 4 + 4096 + 64 * 3) * 4;           // ~86.8 KB

    cudaFuncSetAttribute(kv_kernel,    cudaFuncAttributeMaxDynamicSharedMemorySize, SM_B);
    cudaFuncSetAttribute(mprep_kernel, cudaFuncAttributeMaxDynamicSharedMemorySize, SM_C);
    cudaFuncSetAttribute(out_kernel,   cudaFuncAttributeMaxDynamicSharedMemorySize, SM_D);

    kv_kernel<<<dim3(BHn, NSPLIT), 256, SM_B>>>(key, value, wk_w, wk_b, wv_w, wv_b);
    mprep_kernel<<<BHn, 256, SM_C>>>(dense_w);
    out_kernel<<<dim3(Sn / 64, Bn), 256, SM_D>>>(query, wq_w, wq_b, dense_b, out);
}

// round 2
// speedup vs baseline: 1.3682x; 1.3682x over previous
#include <cuda_runtime.h>

// ---------------- problem constants ----------------
constexpr int Bn = 4;
constexpr int Sn = 4096;
constexpr int Hn = 16;
constexpr int BHn = 64;
constexpr int NSPLIT = 8;
constexpr int SCHUNK = Sn / NSPLIT;   // 512
constexpr int CH  = 32;               // s-rows per staged chunk
constexpr int NCH = SCHUNK / CH;      // 16
constexpr int PAD  = 68;              // raw-tile row stride (floats), 17 float4
constexpr int APAD = 132;             // stacked-tile row stride (floats), 33 float4
constexpr float PIC = 3.1415f;        // verbatim constant from reference

// ---------------- static device scratch ----------------
// stacked partials: slot(16) x bh(64) x [128 rows x 64 cols] as float4
__device__ float4 g_part[16 * 64 * 2048];
__device__ float  g_partKs[8 * 64 * 128];   // split(8) x bh x stacked-ksum(128)
__device__ float4 g_Mst[64 * 2048];         // bh x [128 x 64]  ([M;Mp] folded)
__device__ float  g_Ks [64 * 128];          // bh x stacked [Ksum;Kpsum]

// ---------------- packed fp32x2 helpers ----------------
using ull = unsigned long long;
__device__ __forceinline__ ull pack2(float x, float y) {
    ull r; asm("mov.b64 %0,{%1,%2};" : "=l"(r) : "f"(x), "f"(y)); return r;
}
__device__ __forceinline__ ull bc2(float x) { return pack2(x, x); }
__device__ __forceinline__ void fma2(ull& d, ull a, ull b) {
    asm("fma.rn.f32x2 %0,%1,%2,%0;" : "+l"(d) : "l"(a), "l"(b));
}
__device__ __forceinline__ float2 up2(ull v) {
    float2 r; asm("mov.b64 {%0,%1},%2;" : "=f"(r.x), "=f"(r.y) : "l"(v)); return r;
}
__device__ __forceinline__ float elu1(float v) { return v > 0.f ? v + 1.f : __expf(v); }

// ===========================================================================
// Kernel 1: per (bh, split) — project Kp = elu1(rawK@Wk_h + bk); accumulate
//   stacked C[128][64]: rows 0-63  = Kp^T @ rawV        (KVraw)
//                       rows 64-127= (sin·Kp)^T @ rawV  (KVpraw)
//   plus stacked column sums [Ksum;Kpsum]. V is NOT projected (folded later).
// ===========================================================================
__global__ __launch_bounds__(256, 2)
void kv_kernel(const float4* __restrict__ key4, const float4* __restrict__ value4,
               const float* __restrict__ wk_w, const float* __restrict__ wk_b)
{
    extern __shared__ float sm[];
    float* sWk  = sm;                    // 4096
    float* sK   = sWk + 4096;            // 2*CH*PAD = 4352
    float* sV   = sK  + 2 * CH * PAD;    // 4352
    float* sA   = sV  + 2 * CH * PAD;    // CH*APAD = 4224 (stacked kp | kp*sin)
    float* sSin = sA  + CH * APAD;       // 64 (double buffered)

    float4* sK4 = (float4*)sK;
    float4* sV4 = (float4*)sV;
    float4* sA4 = (float4*)sA;

    const int bh = blockIdx.x, split = blockIdx.y;
    const int b  = bh >> 4,   h     = bh & 15;
    const int tid = threadIdx.x;
    const int sbase = split * SCHUNK;

    // head K-weight slice -> smem
    #pragma unroll
    for (int t = 0; t < 16; t++) {
        int i = tid + t * 256;
        sWk[i] = wk_w[(i >> 6) * 1024 + h * 64 + (i & 63)];
    }

    // projection thread mapping
    const int pr = tid >> 3;          // row 0..31
    const int pc = (tid & 7) * 8;     // 8 cols
    ull bk2[4];
    #pragma unroll
    for (int j = 0; j < 4; j++)
        bk2[j] = pack2(wk_b[h * 64 + pc + 2 * j], wk_b[h * 64 + pc + 2 * j + 1]);

    // accumulation thread mapping: 2 S-groups of 128 threads, 8x8 tiles over 128x64
    const int g  = tid >> 7;
    const int t7 = tid & 127;
    const int ty = t7 >> 3;           // 0..15 -> 8 stacked rows each
    const int tx = t7 & 7;            // -> 8 v-cols

    ull acc[32];                      // 8 rows x 8 cols packed as 8x4 ull
    #pragma unroll
    for (int j = 0; j < 32; j++) acc[j] = 0ull;
    float kcol[8], kpcol[8];
    #pragma unroll
    for (int j = 0; j < 8; j++) { kcol[j] = 0.f; kpcol[j] = 0.f; }

    // prologue: stage chunk 0
    float4 rk[2], rv[2];
    #pragma unroll
    for (int t = 0; t < 2; t++) {
        int i = tid + t * 256; int r = i >> 4, c4 = i & 15;
        size_t gidx = ((size_t)(b * Sn + sbase + r)) * 16 + c4;
        rk[t] = key4[gidx]; rv[t] = value4[gidx];
    }
    #pragma unroll
    for (int t = 0; t < 2; t++) {
        int i = tid + t * 256; int r = i >> 4, c4 = i & 15;
        sK4[r * 17 + c4] = rk[t]; sV4[r * 17 + c4] = rv[t];
    }
    if (tid < 32) sSin[tid] = sinf(PIC * (float)(sbase + tid) / (float)Sn);
    __syncthreads();

    for (int c = 0; c < NCH; c++) {
        const int buf = c & 1;

        // ---- projection: kp row pr, cols pc..pc+7 ----
        {
            ull a2[4];
            #pragma unroll
            for (int j = 0; j < 4; j++) a2[j] = bk2[j];
            const float4* kr = &sK4[buf * CH * 17 + pr * 17];
            #pragma unroll
            for (int k4 = 0; k4 < 16; k4++) {
                float4 a4 = kr[k4];
                #pragma unroll
                for (int u = 0; u < 4; u++) {
                    float av = (u == 0) ? a4.x : (u == 1) ? a4.y : (u == 2) ? a4.z : a4.w;
                    ull au = bc2(av);
                    const ulonglong2* w2 = (const ulonglong2*)&sWk[(k4 * 4 + u) * 64 + pc];
                    ulonglong2 wA = w2[0], wB = w2[1];
                    fma2(a2[0], au, wA.x); fma2(a2[1], au, wA.y);
                    fma2(a2[2], au, wB.x); fma2(a2[3], au, wB.y);
                }
            }
            float kp[8];
            #pragma unroll
            for (int j = 0; j < 4; j++) {
                float2 f = up2(a2[j]);
                kp[2 * j] = elu1(f.x); kp[2 * j + 1] = elu1(f.y);
            }
            float s = sSin[buf * 32 + pr];
            #pragma unroll
            for (int j = 0; j < 8; j++) { kcol[j] += kp[j]; kpcol[j] += kp[j] * s; }
            float4* d0 = (float4*)&sA[pr * APAD + pc];
            d0[0] = make_float4(kp[0], kp[1], kp[2], kp[3]);
            d0[1] = make_float4(kp[4], kp[5], kp[6], kp[7]);
            float4* d1 = (float4*)&sA[pr * APAD + 64 + pc];
            d1[0] = make_float4(kp[0]*s, kp[1]*s, kp[2]*s, kp[3]*s);
            d1[1] = make_float4(kp[4]*s, kp[5]*s, kp[6]*s, kp[7]*s);
        }

        // prefetch next chunk to regs (overlaps with accumulation latency)
        if (c + 1 < NCH) {
            #pragma unroll
            for (int t = 0; t < 2; t++) {
                int i = tid + t * 256; int r = i >> 4, c4 = i & 15;
                size_t gidx = ((size_t)(b * Sn + sbase + (c + 1) * CH + r)) * 16 + c4;
                rk[t] = key4[gidx]; rv[t] = value4[gidx];
            }
        }
        __syncthreads();

        // ---- accumulation: 8x8 register tile, packed FFMA2 ----
        {
            #pragma unroll 4
            for (int ss = g * 16; ss < g * 16 + 16; ss++) {
                float4 a0 = sA4[ss * 33 + ty * 2];
                float4 a1 = sA4[ss * 33 + ty * 2 + 1];
                const float* vrow = &sV[(buf * CH + ss) * PAD + tx * 8];
                ulonglong2 B0 = *(const ulonglong2*)(vrow);
                ulonglong2 B1 = *(const ulonglong2*)(vrow + 4);
                ull A[8] = { bc2(a0.x), bc2(a0.y), bc2(a0.z), bc2(a0.w),
                             bc2(a1.x), bc2(a1.y), bc2(a1.z), bc2(a1.w) };
                ull Bv[4] = { B0.x, B0.y, B1.x, B1.y };
                #pragma unroll
                for (int i = 0; i < 8; i++)
                    #pragma unroll
                    for (int j = 0; j < 4; j++) fma2(acc[i * 4 + j], A[i], Bv[j]);
            }
        }

        // store next chunk to the other buffer
        if (c + 1 < NCH) {
            const int nb = buf ^ 1;
            #pragma unroll
            for (int t = 0; t < 2; t++) {
                int i = tid + t * 256; int r = i >> 4, c4 = i & 15;
                sK4[nb * CH * 17 + r * 17 + c4] = rk[t];
                sV4[nb * CH * 17 + r * 17 + c4] = rv[t];
            }
            if (tid < 32)
                sSin[nb * 32 + tid] = sinf(PIC * (float)(sbase + (c + 1) * CH + tid) / (float)Sn);
        }
        __syncthreads();
    }

    // write stacked C partial (slot = split*2 + g)
    {
        size_t base = ((size_t)((split * 2 + g) * 64 + bh)) * 2048;
        #pragma unroll
        for (int i = 0; i < 8; i++) {
            int m = ty * 8 + i;
            float2 p0 = up2(acc[i*4+0]), p1 = up2(acc[i*4+1]);
            float2 p2 = up2(acc[i*4+2]), p3 = up2(acc[i*4+3]);
            g_part[base + m * 16 + tx * 2    ] = make_float4(p0.x, p0.y, p1.x, p1.y);
            g_part[base + m * 16 + tx * 2 + 1] = make_float4(p2.x, p2.y, p3.x, p3.y);
        }
    }

    // ksum partials: stash per-thread column sums into sA, reduce over rows
    #pragma unroll
    for (int j = 0; j < 8; j++) {
        sA[pr * APAD + pc + j]      = kcol[j];
        sA[pr * APAD + 64 + pc + j] = kpcol[j];
    }
    __syncthreads();
    if (tid < 128) {
        float s = 0.f;
        #pragma unroll
        for (int r = 0; r < 32; r++) s += sA[r * APAD + tid];
        g_partKs[(split * 64 + bh) * 128 + tid] = s;
    }
}

// ===========================================================================
// Kernel 2: per bh — reduce partials (fixed order), fold V-proj + dense:
//   G = Wv_h @ Wd_h ; bvd = bv_h @ Wd_h
//   [M;Mp] = Craw @ G + [Ksum;Kpsum] (outer) bvd ; finalize stacked Ksum.
// ===========================================================================
__global__ __launch_bounds__(256)
void mprep_kernel(const float* __restrict__ wv_w, const float* __restrict__ wv_b,
                  const float* __restrict__ dense_w)
{
    extern __shared__ float sm[];
    float* sC    = sm;                   // 128*PAD = 8704
    float* sWv   = sC   + 128 * PAD;     // 64*PAD = 4352
    float* sWd   = sWv  + 64 * PAD;      // 4352
    float* sG    = sWd  + 64 * PAD;      // 4352
    float* sKsum = sG   + 64 * PAD;      // 128
    float* sBvd  = sKsum + 128;          // 64
    float4* sC4 = (float4*)sC;

    const int bh = blockIdx.x, h = bh & 15, tid = threadIdx.x;

    #pragma unroll
    for (int t = 0; t < 16; t++) {
        int i = tid + t * 256; int k = i >> 6, c = i & 63;
        sWv[k * PAD + c] = wv_w[k * 1024 + h * 64 + c];
        sWd[k * PAD + c] = dense_w[(h * 64 + k) * 64 + c];
    }
    #pragma unroll
    for (int t = 0; t < 8; t++) {
        int idx = tid + t * 256; int r = idx >> 4, c4 = idx & 15;
        float4 s = make_float4(0.f, 0.f, 0.f, 0.f);
        for (int sl = 0; sl < 16; sl++) {
            float4 v = g_part[((size_t)(sl * 64 + bh)) * 2048 + idx];
            s.x += v.x; s.y += v.y; s.z += v.z; s.w += v.w;
        }
        sC4[r * 17 + c4] = s;
    }
    if (tid < 128) {
        float s = 0.f;
        for (int sl = 0; sl < 8; sl++) s += g_partKs[(sl * 64 + bh) * 128 + tid];
        sKsum[tid] = s;
        g_Ks[bh * 128 + tid] = s;
    }
    __syncthreads();

    const int r  = tid >> 2;
    const int c0 = (tid & 3) * 16;

    // G = Wv @ Wd
    {
        float a16[16];
        #pragma unroll
        for (int j = 0; j < 16; j++) a16[j] = 0.f;
        for (int kk = 0; kk < 64; kk++) {
            float a = sWv[r * PAD + kk];
            #pragma unroll
            for (int j = 0; j < 16; j++) a16[j] += a * sWd[kk * PAD + c0 + j];
        }
        #pragma unroll
        for (int j = 0; j < 16; j++) sG[r * PAD + c0 + j] = a16[j];
    }
    if (tid < 64) {
        float s = 0.f;
        for (int c = 0; c < 64; c++) s += wv_b[h * 64 + c] * sWd[c * PAD + tid];
        sBvd[tid] = s;
    }
    __syncthreads();

    // [M;Mp] = sC @ sG + ksum (outer) bvd
    {
        float m0[16], m1[16];
        #pragma unroll
        for (int j = 0; j < 16; j++) { m0[j] = 0.f; m1[j] = 0.f; }
        for (int kk = 0; kk < 64; kk++) {
            float a0 = sC[r * PAD + kk];
            float a1 = sC[(r + 64) * PAD + kk];
            #pragma unroll
            for (int j = 0; j < 16; j++) {
                float gv = sG[kk * PAD + c0 + j];
                m0[j] += a0 * gv; m1[j] += a1 * gv;
            }
        }
        float k0 = sKsum[r], k1 = sKsum[r + 64];
        #pragma unroll
        for (int j = 0; j < 16; j++) {
            m0[j] += k0 * sBvd[c0 + j];
            m1[j] += k1 * sBvd[c0 + j];
        }
        size_t ob0 = (size_t)bh * 2048 + r * 16 + (c0 >> 2);
        size_t ob1 = (size_t)bh * 2048 + (r + 64) * 16 + (c0 >> 2);
        #pragma unroll
        for (int jj = 0; jj < 4; jj++) {
            g_Mst[ob0 + jj] = make_float4(m0[4*jj], m0[4*jj+1], m0[4*jj+2], m0[4*jj+3]);
            g_Mst[ob1 + jj] = make_float4(m1[4*jj], m1[4*jj+1], m1[4*jj+2], m1[4*jj+3]);
        }
    }
}

// ===========================================================================
// Kernel 3: per (b, 64-row s-tile) — q projection + denom + stacked o-GEMM:
//   out[s] = dense_b + sum_h den_sh * [q | w_s*q] @ [M_h; Mp_h]
// ===========================================================================
__global__ __launch_bounds__(256, 2)
void out_kernel(const float4* __restrict__ query4,
                const float4* __restrict__ wq_w4, const float* __restrict__ wq_b,
                const float* __restrict__ dense_b, float4* __restrict__ out4)
{
    extern __shared__ float sm[];
    float* sRawQ = sm;                    // 64*PAD = 4352
    float* sWq   = sRawQ + 64 * PAD;      // 4096
    float* sB    = sWq   + 4096;          // 128*PAD = 8704
    float* sQs   = sB    + 128 * PAD;     // 64*APAD = 8448
    float* sKs   = sQs   + 64 * APAD;     // 128
    float* sW    = sKs   + 128;           // 64
    float* sQb   = sW    + 64;            // 64
    float4* sRawQ4 = (float4*)sRawQ;
    float4* sWq4   = (float4*)sWq;
    float4* sB4    = (float4*)sB;
    float4* sQs4   = (float4*)sQs;

    const int b  = blockIdx.y;
    const int s0 = blockIdx.x * 64;
    const int tid  = threadIdx.x;
    const int srow = tid >> 2;
    const int c0   = (tid & 3) * 16;

    #pragma unroll
    for (int t = 0; t < 4; t++) {
        int i = tid + t * 256; int r = i >> 4, c4 = i & 15;
        sRawQ4[r * 17 + c4] = query4[((size_t)(b * Sn + s0 + r)) * 16 + c4];
    }
    if (tid < 64) {
        float ps = PIC * (float)(s0 + tid) / (float)Sn;
        sW[tid] = cosf(ps) + sinf(ps);
    }

    ull accO[8];
    #pragma unroll
    for (int j = 0; j < 8; j++) accO[j] = 0ull;

    for (int h = 0; h < Hn; h++) {
        const int bh = b * 16 + h;
        #pragma unroll
        for (int t = 0; t < 4; t++) {
            int i = tid + t * 256; int k = i >> 4, c4 = i & 15;
            sWq4[i] = wq_w4[k * 256 + h * 16 + c4];
        }
        #pragma unroll
        for (int t = 0; t < 8; t++) {
            int idx = tid + t * 256; int r = idx >> 4, c4 = idx & 15;
            sB4[r * 17 + c4] = g_Mst[(size_t)bh * 2048 + idx];
        }
        if (tid < 128)      sKs[tid] = g_Ks[bh * 128 + tid];
        else if (tid < 192) sQb[tid - 128] = wq_b[h * 64 + (tid - 128)];
        __syncthreads();

        // ---- q projection (row srow, cols c0..c0+15) ----
        float q[16];
        {
            ull a2[8];
            #pragma unroll
            for (int j = 0; j < 8; j++)
                a2[j] = pack2(sQb[c0 + 2 * j], sQb[c0 + 2 * j + 1]);
            #pragma unroll
            for (int k4 = 0; k4 < 16; k4++) {
                float4 a4 = sRawQ4[srow * 17 + k4];
                #pragma unroll
                for (int u = 0; u < 4; u++) {
                    float av = (u == 0) ? a4.x : (u == 1) ? a4.y : (u == 2) ? a4.z : a4.w;
                    ull au = bc2(av);
                    const ulonglong2* w2 = (const ulonglong2*)&sWq[(k4 * 4 + u) * 64 + c0];
                    ulonglong2 wA = w2[0], wB = w2[1], wC = w2[2], wD = w2[3];
                    fma2(a2[0], au, wA.x); fma2(a2[1], au, wA.y);
                    fma2(a2[2], au, wB.x); fma2(a2[3], au, wB.y);
                    fma2(a2[4], au, wC.x); fma2(a2[5], au, wC.y);
                    fma2(a2[6], au, wD.x); fma2(a2[7], au, wD.y);
                }
            }
            #pragma unroll
            for (int j = 0; j < 8; j++) {
                float2 f = up2(a2[j]);
                q[2 * j] = elu1(f.x); q[2 * j + 1] = elu1(f.y);
            }
        }
        const float w = sW[srow];

        // ---- denominator: quad reduction over the 4 col-groups of this row ----
        float d0 = 0.f, d1 = 0.f;
        #pragma unroll
        for (int j = 0; j < 16; j++) {
            d0 += q[j] * sKs[c0 + j];
            d1 += q[j] * sKs[64 + c0 + j];
        }
        d0 += __shfl_xor_sync(0xffffffffu, d0, 1);
        d0 += __shfl_xor_sync(0xffffffffu, d0, 2);
        d1 += __shfl_xor_sync(0xffffffffu, d1, 1);
        d1 += __shfl_xor_sync(0xffffffffu, d1, 2);
        const float den = 1.0f / (d0 + w * d1 + 1e-5f);

        // ---- store stacked [q | w*q] ----
        {
            float4* dq = (float4*)&sQs[srow * APAD + c0];
            dq[0] = make_float4(q[0],  q[1],  q[2],  q[3]);
            dq[1] = make_float4(q[4],  q[5],  q[6],  q[7]);
            dq[2] = make_float4(q[8],  q[9],  q[10], q[11]);
            dq[3] = make_float4(q[12], q[13], q[14], q[15]);
            float4* dw = (float4*)&sQs[srow * APAD + 64 + c0];
            dw[0] = make_float4(q[0]*w,  q[1]*w,  q[2]*w,  q[3]*w);
            dw[1] = make_float4(q[4]*w,  q[5]*w,  q[6]*w,  q[7]*w);
            dw[2] = make_float4(q[8]*w,  q[9]*w,  q[10]*w, q[11]*w);
            dw[3] = make_float4(q[12]*w, q[13]*w, q[14]*w, q[15]*w);
        }
        __syncthreads();

        // ---- stacked o-GEMM: ot = A[srow] @ B (K=128) ----
        ull ot[8];
        #pragma unroll
        for (int j = 0; j < 8; j++) ot[j] = 0ull;
        #pragma unroll 4
        for (int k4 = 0; k4 < 32; k4++) {
            float4 a4 = sQs4[srow * 33 + k4];
            #pragma unroll
            for (int u = 0; u < 4; u++) {
                float av = (u == 0) ? a4.x : (u == 1) ? a4.y : (u == 2) ? a4.z : a4.w;
                ull au = bc2(av);
                const ulonglong2* B2 = (const ulonglong2*)&sB[(k4 * 4 + u) * PAD + c0];
                ulonglong2 bA = B2[0], bB = B2[1], bC = B2[2], bD = B2[3];
                fma2(ot[0], au, bA.x); fma2(ot[1], au, bA.y);
                fma2(ot[2], au, bB.x); fma2(ot[3], au, bB.y);
                fma2(ot[4], au, bC.x); fma2(ot[5], au, bC.y);
                fma2(ot[6], au, bD.x); fma2(ot[7], au, bD.y);
            }
        }
        ull den2 = bc2(den);
        #pragma unroll
        for (int j = 0; j < 8; j++) fma2(accO[j], den2, ot[j]);
        __syncthreads();
    }

    // epilogue: + dense_b, single write
    {
        size_t ob = ((size_t)(b * Sn + s0 + srow)) * 16 + (c0 >> 2);
        #pragma unroll
        for (int jj = 0; jj < 4; jj++) {
            float2 pa = up2(accO[2 * jj]), pb = up2(accO[2 * jj + 1]);
            out4[ob + jj] = make_float4(pa.x + dense_b[c0 + 4*jj],
                                        pa.y + dense_b[c0 + 4*jj + 1],
                                        pb.x + dense_b[c0 + 4*jj + 2],
                                        pb.y + dense_b[c0 + 4*jj + 3]);
        }
    }
}

// ---------------------------------------------------------------------------
extern "C" void kernel_launch(void* const* d_in, const int* in_sizes, int n_in,
                              void* d_out, int out_size)
{
    const float4* query4  = (const float4*)d_in[0];
    const float4* key4    = (const float4*)d_in[1];
    const float4* value4  = (const float4*)d_in[2];
    // d_in[3] = attn_mask (unused by the math)
    const float4* wq_w4   = (const float4*)d_in[4];
    const float*  wq_b    = (const float*)d_in[5];
    const float*  wk_w    = (const float*)d_in[6];
    const float*  wk_b    = (const float*)d_in[7];
    const float*  wv_w    = (const float*)d_in[8];
    const float*  wv_b    = (const float*)d_in[9];
    const float*  dense_w = (const float*)d_in[10];
    const float*  dense_b = (const float*)d_in[11];
    float4* out4 = (float4*)d_out;

    constexpr int SM_KV  = (4096 + 2*CH*PAD*2 + CH*APAD + 64) * 4;            // 68,352 B
    constexpr int SM_MP  = (128*PAD + 3*64*PAD + 128 + 64) * 4;               // 87,808 B
    constexpr int SM_OUT = (64*PAD + 4096 + 128*PAD + 64*APAD + 256) * 4;     // 103,424 B

    cudaFuncSetAttribute(kv_kernel,    cudaFuncAttributeMaxDynamicSharedMemorySize, SM_KV);
    cudaFuncSetAttribute(mprep_kernel, cudaFuncAttributeMaxDynamicSharedMemorySize, SM_MP);
    cudaFuncSetAttribute(out_kernel,   cudaFuncAttributeMaxDynamicSharedMemorySize, SM_OUT);

    kv_kernel  <<<dim3(BHn, NSPLIT), 256, SM_KV >>>(key4, value4, wk_w, wk_b);
    mprep_kernel<<<BHn,              256, SM_MP >>>(wv_w, wv_b, dense_w);
    out_kernel <<<dim3(Sn / 64, Bn), 256, SM_OUT>>>(query4, wq_w4, wq_b, dense_b, out4);
}

// round 3
// speedup vs baseline: 3.7897x; 2.7699x over previous
#include <cuda_runtime.h>

// ---------------- problem constants ----------------
constexpr int Bn = 4;
constexpr int Sn = 4096;
constexpr int Hn = 16;
constexpr int BHn = 64;
constexpr int NSPLIT = 8;
constexpr int SCHUNK = Sn / NSPLIT;   // 512
constexpr int CH  = 64;               // s-rows per staged chunk
constexpr int NCH = SCHUNK / CH;      // 8
constexpr int PAD  = 68;              // row stride (floats) for 64-wide tiles
constexpr int APAD = 132;             // row stride (floats) for 128-wide stacked tiles
constexpr float PIC = 3.1415f;        // verbatim constant from reference

// ---------------- static device scratch ----------------
__device__ float4 g_part[16 * 64 * 2048];   // slot(16) x bh x [128x64] stacked KV partials
__device__ float  g_partKs[8 * 64 * 128];   // split(8) x bh x stacked ksum(128)
__device__ float4 g_Mst[64 * 2048];         // bh x [128 x 64]  ([M;Mp] with dense fold)
__device__ float  g_Ks [64 * 128];          // bh x stacked [Ksum;Kpsum]

// ---------------- packed fp32x2 helpers ----------------
using ull = unsigned long long;
__device__ __forceinline__ ull pack2(float x, float y) {
    ull r; asm("mov.b64 %0,{%1,%2};" : "=l"(r) : "f"(x), "f"(y)); return r;
}
__device__ __forceinline__ ull bc2(float x) { return pack2(x, x); }
__device__ __forceinline__ void fma2(ull& d, ull a, ull b) {
    asm("fma.rn.f32x2 %0,%1,%2,%0;" : "+l"(d) : "l"(a), "l"(b));
}
__device__ __forceinline__ void add2(ull& d, ull a) {
    asm("add.rn.f32x2 %0,%0,%1;" : "+l"(d) : "l"(a));
}
__device__ __forceinline__ float2 up2(ull v) {
    float2 r; asm("mov.b64 {%0,%1},%2;" : "=f"(r.x), "=f"(r.y) : "l"(v)); return r;
}
__device__ __forceinline__ float elu1(float v) { return v > 0.f ? v + 1.f : __expf(v); }

// ===========================================================================
// Kernel 1: per (bh, split) — Kp = elu1(rawK@Wk_h + bk); accumulate stacked
//   C[128][64]: rows 0-63 = Kp^T@rawV, rows 64-127 = (sin*Kp)^T@rawV,
//   plus stacked column sums [Ksum;Kpsum] (harvested inside accum loop).
// ===========================================================================
__global__ __launch_bounds__(256, 2)
void kv_kernel(const float4* __restrict__ key4, const float4* __restrict__ value4,
               const float4* __restrict__ wk_w4, const float* __restrict__ wk_b)
{
    extern __shared__ float sm[];
    float* sWk  = sm;                 // 64 x 68 = 4352
    float* sK   = sWk + 4352;         // 64 x 68
    float* sV   = sK  + 4352;         // 64 x 68
    float* sA   = sV  + 4352;         // 64 x 132 = 8448 (stacked kp | kp*sin)
    float* sRed = sA  + 8448;         // 128 x 36 = 4608 (k-split reduce scratch)
    float* sSin = sRed + 4608;        // 64

    float4* sWk4 = (float4*)sWk;
    float4* sK4  = (float4*)sK;
    float4* sV4  = (float4*)sV;
    float4* sA4  = (float4*)sA;

    const int bh = blockIdx.x, split = blockIdx.y;
    const int b  = bh >> 4,   h     = bh & 15;
    const int tid = threadIdx.x;
    const int sbase = split * SCHUNK;

    // head K-weight slice -> smem [k][c] padded
    #pragma unroll
    for (int t = 0; t < 4; t++) {
        int idx = tid + t * 256;                // float4 index over 64x16
        int k = idx >> 4, c4 = idx & 15;
        sWk4[k * 17 + c4] = wk_w4[k * 256 + h * 16 + c4];
    }

    // thread mapping (shared by proj & accum): 2 groups of 128
    const int g   = tid >> 7;
    const int pos = tid & 127;
    const int rg  = pos >> 3;      // proj: rows 4rg..4rg+3 ; accum: stacked rows 8rg..
    const int cg  = pos & 7;       // proj: cols 8cg..      ; accum: v-cols 8cg..
    const int k0  = g * 32;        // proj k-half

    ull bk2[4];
    #pragma unroll
    for (int j = 0; j < 4; j++)
        bk2[j] = (g == 0) ? pack2(wk_b[h * 64 + cg * 8 + 2 * j],
                                  wk_b[h * 64 + cg * 8 + 2 * j + 1]) : 0ull;

    ull acc[32];                   // accum 8x8 tile (8 rows x 4 packed cols)
    #pragma unroll
    for (int j = 0; j < 32; j++) acc[j] = 0ull;
    ull ks2[4];                    // stacked ksum partial (cols 8rg..8rg+7), tx==0 only
    #pragma unroll
    for (int j = 0; j < 4; j++) ks2[j] = 0ull;

    // stage chunk 0
    {
        #pragma unroll
        for (int t = 0; t < 4; t++) {
            int idx = tid + t * 256; int r = idx >> 4, c4 = idx & 15;
            size_t gi = ((size_t)(b * Sn + sbase + r)) * 16 + c4;
            sK4[r * 17 + c4] = key4[gi];
            sV4[r * 17 + c4] = value4[gi];
        }
        if (tid < 64) sSin[tid] = sinf(PIC * (float)(sbase + tid) / (float)Sn);
    }
    __syncthreads();

    for (int c = 0; c < NCH; c++) {
        // ---- projection partial: rows 4rg..+3, cols 8cg..+7, k in [k0,k0+32) ----
        ull pa[16];
        #pragma unroll
        for (int i = 0; i < 4; i++)
            #pragma unroll
            for (int jj = 0; jj < 4; jj++) pa[i * 4 + jj] = bk2[jj];
        #pragma unroll 4
        for (int kk = k0; kk < k0 + 32; kk++) {
            float a0 = sK[(4 * rg + 0) * PAD + kk];
            float a1 = sK[(4 * rg + 1) * PAD + kk];
            float a2 = sK[(4 * rg + 2) * PAD + kk];
            float a3 = sK[(4 * rg + 3) * PAD + kk];
            ulonglong2 wA = *(const ulonglong2*)&sWk[kk * PAD + 8 * cg];
            ulonglong2 wB = *(const ulonglong2*)&sWk[kk * PAD + 8 * cg + 4];
            ull u0 = bc2(a0), u1 = bc2(a1), u2 = bc2(a2), u3 = bc2(a3);
            fma2(pa[0],  u0, wA.x); fma2(pa[1],  u0, wA.y); fma2(pa[2],  u0, wB.x); fma2(pa[3],  u0, wB.y);
            fma2(pa[4],  u1, wA.x); fma2(pa[5],  u1, wA.y); fma2(pa[6],  u1, wB.x); fma2(pa[7],  u1, wB.y);
            fma2(pa[8],  u2, wA.x); fma2(pa[9],  u2, wA.y); fma2(pa[10], u2, wB.x); fma2(pa[11], u2, wB.y);
            fma2(pa[12], u3, wA.x); fma2(pa[13], u3, wA.y); fma2(pa[14], u3, wB.x); fma2(pa[15], u3, wB.y);
        }
        if (g == 1) {
            float4* d = (float4*)&sRed[pos * 36];
            #pragma unroll
            for (int i = 0; i < 4; i++) {
                float2 f0 = up2(pa[i*4+0]), f1 = up2(pa[i*4+1]);
                float2 f2 = up2(pa[i*4+2]), f3 = up2(pa[i*4+3]);
                d[i * 2]     = make_float4(f0.x, f0.y, f1.x, f1.y);
                d[i * 2 + 1] = make_float4(f2.x, f2.y, f3.x, f3.y);
            }
        }
        __syncthreads();
        if (g == 0) {
            const float4* r4 = (const float4*)&sRed[pos * 36];
            #pragma unroll
            for (int i = 0; i < 4; i++) {
                float4 q0 = r4[i * 2], q1 = r4[i * 2 + 1];
                float2 f;
                float kp[8];
                f = up2(pa[i*4+0]); kp[0] = elu1(f.x + q0.x); kp[1] = elu1(f.y + q0.y);
                f = up2(pa[i*4+1]); kp[2] = elu1(f.x + q0.z); kp[3] = elu1(f.y + q0.w);
                f = up2(pa[i*4+2]); kp[4] = elu1(f.x + q1.x); kp[5] = elu1(f.y + q1.y);
                f = up2(pa[i*4+3]); kp[6] = elu1(f.x + q1.z); kp[7] = elu1(f.y + q1.w);
                float ss = sSin[4 * rg + i];
                float4* d0 = (float4*)&sA[(4 * rg + i) * APAD + 8 * cg];
                d0[0] = make_float4(kp[0], kp[1], kp[2], kp[3]);
                d0[1] = make_float4(kp[4], kp[5], kp[6], kp[7]);
                float4* d1 = (float4*)&sA[(4 * rg + i) * APAD + 64 + 8 * cg];
                d1[0] = make_float4(kp[0]*ss, kp[1]*ss, kp[2]*ss, kp[3]*ss);
                d1[1] = make_float4(kp[4]*ss, kp[5]*ss, kp[6]*ss, kp[7]*ss);
            }
        }
        __syncthreads();

        // ---- accumulation: ss in [g*32, g*32+32), 8x8 tile + free ksum ----
        #pragma unroll 4
        for (int ss = g * 32; ss < g * 32 + 32; ss++) {
            float4 a0 = sA4[ss * 33 + rg * 2];
            float4 a1 = sA4[ss * 33 + rg * 2 + 1];
            const float* vrow = &sV[ss * PAD + cg * 8];
            ulonglong2 B0 = *(const ulonglong2*)(vrow);
            ulonglong2 B1 = *(const ulonglong2*)(vrow + 4);
            ull A[8] = { bc2(a0.x), bc2(a0.y), bc2(a0.z), bc2(a0.w),
                         bc2(a1.x), bc2(a1.y), bc2(a1.z), bc2(a1.w) };
            ull Bv[4] = { B0.x, B0.y, B1.x, B1.y };
            #pragma unroll
            for (int i = 0; i < 8; i++)
                #pragma unroll
                for (int j = 0; j < 4; j++) fma2(acc[i * 4 + j], A[i], Bv[j]);
            if (cg == 0) {
                add2(ks2[0], pack2(a0.x, a0.y)); add2(ks2[1], pack2(a0.z, a0.w));
                add2(ks2[2], pack2(a1.x, a1.y)); add2(ks2[3], pack2(a1.z, a1.w));
            }
        }
        __syncthreads();

        if (c + 1 < NCH) {
            #pragma unroll
            for (int t = 0; t < 4; t++) {
                int idx = tid + t * 256; int r = idx >> 4, c4 = idx & 15;
                size_t gi = ((size_t)(b * Sn + sbase + (c + 1) * CH + r)) * 16 + c4;
                sK4[r * 17 + c4] = key4[gi];
                sV4[r * 17 + c4] = value4[gi];
            }
            if (tid < 64)
                sSin[tid] = sinf(PIC * (float)(sbase + (c + 1) * CH + tid) / (float)Sn);
        }
        __syncthreads();
    }

    // write stacked C partial (slot = split*2 + g)
    {
        size_t base = ((size_t)((split * 2 + g) * 64 + bh)) * 2048;
        #pragma unroll
        for (int i = 0; i < 8; i++) {
            int m = rg * 8 + i;
            float2 p0 = up2(acc[i*4+0]), p1 = up2(acc[i*4+1]);
            float2 p2 = up2(acc[i*4+2]), p3 = up2(acc[i*4+3]);
            g_part[base + m * 16 + cg * 2    ] = make_float4(p0.x, p0.y, p1.x, p1.y);
            g_part[base + m * 16 + cg * 2 + 1] = make_float4(p2.x, p2.y, p3.x, p3.y);
        }
    }

    // stacked ksum: tx==0 threads hold cols 8rg..+7 partials; reduce the 2 groups
    if (cg == 0) {
        #pragma unroll
        for (int j = 0; j < 4; j++) {
            float2 f = up2(ks2[j]);
            sA[(g * 16 + rg) * APAD + 2 * j]     = f.x;
            sA[(g * 16 + rg) * APAD + 2 * j + 1] = f.y;
        }
    }
    __syncthreads();
    if (tid < 128) {
        float s = sA[((tid >> 3)) * APAD + (tid & 7)]
                + sA[(16 + (tid >> 3)) * APAD + (tid & 7)];
        g_partKs[(split * 64 + bh) * 128 + tid] = s;
    }
}

// ===========================================================================
// Kernel 2: per bh — reduce partials (fixed order), fold V-proj + dense:
//   G = Wv_h @ Wd_h ; bvd = bv_h @ Wd_h
//   [M;Mp] = Craw @ G + [Ksum;Kpsum] (outer) bvd ; finalize stacked Ksum.
// ===========================================================================
__global__ __launch_bounds__(256)
void mprep_kernel(const float* __restrict__ wv_w, const float* __restrict__ wv_b,
                  const float* __restrict__ dense_w)
{
    extern __shared__ float sm[];
    float* sC    = sm;                   // 128*PAD = 8704
    float* sWv   = sC   + 128 * PAD;     // 64*PAD = 4352
    float* sWd   = sWv  + 64 * PAD;      // 4352
    float* sG    = sWd  + 64 * PAD;      // 4352
    float* sKsum = sG   + 64 * PAD;      // 128
    float* sBvd  = sKsum + 128;          // 64
    float4* sC4 = (float4*)sC;

    const int bh = blockIdx.x, h = bh & 15, tid = threadIdx.x;

    #pragma unroll
    for (int t = 0; t < 16; t++) {
        int i = tid + t * 256; int k = i >> 6, c = i & 63;
        sWv[k * PAD + c] = wv_w[k * 1024 + h * 64 + c];
        sWd[k * PAD + c] = dense_w[(h * 64 + k) * 64 + c];
    }
    #pragma unroll
    for (int t = 0; t < 8; t++) {
        int idx = tid + t * 256; int r = idx >> 4, c4 = idx & 15;
        float4 s = make_float4(0.f, 0.f, 0.f, 0.f);
        for (int sl = 0; sl < 16; sl++) {
            float4 v = g_part[((size_t)(sl * 64 + bh)) * 2048 + idx];
            s.x += v.x; s.y += v.y; s.z += v.z; s.w += v.w;
        }
        sC4[r * 17 + c4] = s;
    }
    if (tid < 128) {
        float s = 0.f;
        for (int sl = 0; sl < 8; sl++) s += g_partKs[(sl * 64 + bh) * 128 + tid];
        sKsum[tid] = s;
        g_Ks[bh * 128 + tid] = s;
    }
    __syncthreads();

    const int r  = tid >> 2;
    const int c0 = (tid & 3) * 16;

    // G = Wv @ Wd
    {
        float a16[16];
        #pragma unroll
        for (int j = 0; j < 16; j++) a16[j] = 0.f;
        for (int kk = 0; kk < 64; kk++) {
            float a = sWv[r * PAD + kk];
            #pragma unroll
            for (int j = 0; j < 16; j++) a16[j] += a * sWd[kk * PAD + c0 + j];
        }
        #pragma unroll
        for (int j = 0; j < 16; j++) sG[r * PAD + c0 + j] = a16[j];
    }
    if (tid < 64) {
        float s = 0.f;
        for (int c = 0; c < 64; c++) s += wv_b[h * 64 + c] * sWd[c * PAD + tid];
        sBvd[tid] = s;
    }
    __syncthreads();

    // [M;Mp] = sC @ sG + ksum (outer) bvd
    {
        float m0[16], m1[16];
        #pragma unroll
        for (int j = 0; j < 16; j++) { m0[j] = 0.f; m1[j] = 0.f; }
        for (int kk = 0; kk < 64; kk++) {
            float a0 = sC[r * PAD + kk];
            float a1 = sC[(r + 64) * PAD + kk];
            #pragma unroll
            for (int j = 0; j < 16; j++) {
                float gv = sG[kk * PAD + c0 + j];
                m0[j] += a0 * gv; m1[j] += a1 * gv;
            }
        }
        float k0 = sKsum[r], k1 = sKsum[r + 64];
        #pragma unroll
        for (int j = 0; j < 16; j++) {
            m0[j] += k0 * sBvd[c0 + j];
            m1[j] += k1 * sBvd[c0 + j];
        }
        size_t ob0 = (size_t)bh * 2048 + r * 16 + (c0 >> 2);
        size_t ob1 = (size_t)bh * 2048 + (r + 64) * 16 + (c0 >> 2);
        #pragma unroll
        for (int jj = 0; jj < 4; jj++) {
            g_Mst[ob0 + jj] = make_float4(m0[4*jj], m0[4*jj+1], m0[4*jj+2], m0[4*jj+3]);
            g_Mst[ob1 + jj] = make_float4(m1[4*jj], m1[4*jj+1], m1[4*jj+2], m1[4*jj+3]);
        }
    }
}

// ===========================================================================
// Kernel 3: per (b, 64-row s-tile) — q proj + denom + stacked o-GEMM,
//   4x4 register tiles, A operands transposed in smem for LDS.128 row loads.
//   out[s] = dense_b + sum_h [den*q | den*w*q] @ [M_h; Mp_h]
// ===========================================================================
__global__ __launch_bounds__(256, 2)
void out_kernel(const float4* __restrict__ query4,
                const float4* __restrict__ wq_w4, const float* __restrict__ wq_b,
                const float* __restrict__ dense_b, float4* __restrict__ out4)
{
    extern __shared__ float sm[];
    float* sQrt = sm;             // 64k x 68 (transposed raw Q)      4352
    float* sWq  = sQrt + 4352;    // 64 x 68                          4352
    float* sB   = sWq  + 4352;    // 128 x 68                         8704
    float* sQt  = sB   + 8704;    // 128 x 68 (A^T for o-GEMM)        8704
    float* sKs  = sQt  + 8704;    // 128
    float* sWs  = sKs  + 128;     // 64 (cos+sin)
    float* sQb  = sWs  + 64;      // 64

    float4* sWq4 = (float4*)sWq;
    float4* sB4  = (float4*)sB;

    const int b  = blockIdx.y;
    const int s0 = blockIdx.x * 64;
    const int tid = threadIdx.x;
    const int rg  = tid >> 4;     // rows 4rg..4rg+3
    const int cg  = tid & 15;     // cols 4cg..4cg+3

    // stage raw Q transposed (once per CTA)
    #pragma unroll
    for (int t = 0; t < 4; t++) {
        int idx = tid + t * 256; int r = idx >> 4, c4 = idx & 15;
        float4 v = query4[((size_t)(b * Sn + s0 + r)) * 16 + c4];
        sQrt[(4 * c4 + 0) * PAD + r] = v.x;
        sQrt[(4 * c4 + 1) * PAD + r] = v.y;
        sQrt[(4 * c4 + 2) * PAD + r] = v.z;
        sQrt[(4 * c4 + 3) * PAD + r] = v.w;
    }
    if (tid < 64) {
        float ps = PIC * (float)(s0 + tid) / (float)Sn;
        sWs[tid] = cosf(ps) + sinf(ps);
    }

    ull accO[8];
    #pragma unroll
    for (int j = 0; j < 8; j++) accO[j] = 0ull;
    __syncthreads();

    float wrow[4];
    #pragma unroll
    for (int i = 0; i < 4; i++) wrow[i] = sWs[4 * rg + i];

    for (int h = 0; h < Hn; h++) {
        const int bh = b * 16 + h;
        #pragma unroll
        for (int t = 0; t < 4; t++) {
            int idx = tid + t * 256; int k = idx >> 4, c4 = idx & 15;
            sWq4[k * 17 + c4] = wq_w4[k * 256 + h * 16 + c4];
        }
        #pragma unroll
        for (int t = 0; t < 8; t++) {
            int idx = tid + t * 256; int r = idx >> 4, c4 = idx & 15;
            sB4[r * 17 + c4] = g_Mst[(size_t)bh * 2048 + idx];
        }
        if (tid < 128)      sKs[tid] = g_Ks[bh * 128 + tid];
        else if (tid < 192) sQb[tid - 128] = wq_b[h * 64 + (tid - 128)];
        __syncthreads();

        // ---- q projection: 4x4 tile, K=64 ----
        ull qa[8];
        #pragma unroll
        for (int i = 0; i < 4; i++) {
            qa[i * 2]     = pack2(sQb[4 * cg],     sQb[4 * cg + 1]);
            qa[i * 2 + 1] = pack2(sQb[4 * cg + 2], sQb[4 * cg + 3]);
        }
        #pragma unroll 4
        for (int kk = 0; kk < 64; kk++) {
            float4 a = *(const float4*)&sQrt[kk * PAD + 4 * rg];
            ulonglong2 w = *(const ulonglong2*)&sWq[kk * PAD + 4 * cg];
            fma2(qa[0], bc2(a.x), w.x); fma2(qa[1], bc2(a.x), w.y);
            fma2(qa[2], bc2(a.y), w.x); fma2(qa[3], bc2(a.y), w.y);
            fma2(qa[4], bc2(a.z), w.x); fma2(qa[5], bc2(a.z), w.y);
            fma2(qa[6], bc2(a.w), w.x); fma2(qa[7], bc2(a.w), w.y);
        }
        float q[4][4];
        #pragma unroll
        for (int i = 0; i < 4; i++) {
            float2 f0 = up2(qa[i * 2]), f1 = up2(qa[i * 2 + 1]);
            q[i][0] = elu1(f0.x); q[i][1] = elu1(f0.y);
            q[i][2] = elu1(f1.x); q[i][3] = elu1(f1.y);
        }

        // ---- denominators (shfl over the 16 cg lanes per row) ----
        float4 kA = *(const float4*)&sKs[4 * cg];
        float4 kB = *(const float4*)&sKs[64 + 4 * cg];
        float d0[4], d1[4];
        #pragma unroll
        for (int i = 0; i < 4; i++) {
            d0[i] = q[i][0]*kA.x + q[i][1]*kA.y + q[i][2]*kA.z + q[i][3]*kA.w;
            d1[i] = q[i][0]*kB.x + q[i][1]*kB.y + q[i][2]*kB.z + q[i][3]*kB.w;
        }
        #pragma unroll
        for (int off = 1; off < 16; off <<= 1) {
            #pragma unroll
            for (int i = 0; i < 4; i++) {
                d0[i] += __shfl_xor_sync(0xffffffffu, d0[i], off);
                d1[i] += __shfl_xor_sync(0xffffffffu, d1[i], off);
            }
        }
        float den[4], dnw[4];
        #pragma unroll
        for (int i = 0; i < 4; i++) {
            den[i] = 1.0f / (d0[i] + wrow[i] * d1[i] + 1e-5f);
            dnw[i] = den[i] * wrow[i];
        }

        // ---- store A^T with den folded: sQt[col][row] ----
        #pragma unroll
        for (int j = 0; j < 4; j++) {
            *(float4*)&sQt[(4 * cg + j) * PAD + 4 * rg] =
                make_float4(den[0]*q[0][j], den[1]*q[1][j], den[2]*q[2][j], den[3]*q[3][j]);
            *(float4*)&sQt[(64 + 4 * cg + j) * PAD + 4 * rg] =
                make_float4(dnw[0]*q[0][j], dnw[1]*q[1][j], dnw[2]*q[2][j], dnw[3]*q[3][j]);
        }
        __syncthreads();

        // ---- o-GEMM: 4x4 tile, K=128 ----
        #pragma unroll 4
        for (int kk = 0; kk < 128; kk++) {
            float4 a = *(const float4*)&sQt[kk * PAD + 4 * rg];
            ulonglong2 bb = *(const ulonglong2*)&sB[kk * PAD + 4 * cg];
            fma2(accO[0], bc2(a.x), bb.x); fma2(accO[1], bc2(a.x), bb.y);
            fma2(accO[2], bc2(a.y), bb.x); fma2(accO[3], bc2(a.y), bb.y);
            fma2(accO[4], bc2(a.z), bb.x); fma2(accO[5], bc2(a.z), bb.y);
            fma2(accO[6], bc2(a.w), bb.x); fma2(accO[7], bc2(a.w), bb.y);
        }
        __syncthreads();
    }

    // epilogue: + dense_b, write 4 rows x 1 float4
    float4 db = *(const float4*)&dense_b[4 * cg];
    #pragma unroll
    for (int i = 0; i < 4; i++) {
        float2 p0 = up2(accO[i * 2]), p1 = up2(accO[i * 2 + 1]);
        out4[((size_t)(b * Sn + s0 + 4 * rg + i)) * 16 + cg] =
            make_float4(p0.x + db.x, p0.y + db.y, p1.x + db.z, p1.y + db.w);
    }
}

// ---------------------------------------------------------------------------
extern "C" void kernel_launch(void* const* d_in, const int* in_sizes, int n_in,
                              void* d_out, int out_size)
{
    const float4* query4  = (const float4*)d_in[0];
    const float4* key4    = (const float4*)d_in[1];
    const float4* value4  = (const float4*)d_in[2];
    // d_in[3] = attn_mask (unused by the math)
    const float4* wq_w4   = (const float4*)d_in[4];
    const float*  wq_b    = (const float*)d_in[5];
    const float4* wk_w4   = (const float4*)d_in[6];
    const float*  wk_b    = (const float*)d_in[7];
    const float*  wv_w    = (const float*)d_in[8];
    const float*  wv_b    = (const float*)d_in[9];
    const float*  dense_w = (const float*)d_in[10];
    const float*  dense_b = (const float*)d_in[11];
    float4* out4 = (float4*)d_out;

    constexpr int SM_KV  = (4352 * 3 + 8448 + 4608 + 64) * 4;          // 104,704 B
    constexpr int SM_MP  = (128 * PAD + 3 * 64 * PAD + 128 + 64) * 4;  //  87,808 B
    constexpr int SM_OUT = (4352 * 2 + 8704 * 2 + 128 + 64 + 64) * 4;  // 105,472 B

    cudaFuncSetAttribute(kv_kernel,    cudaFuncAttributeMaxDynamicSharedMemorySize, SM_KV);
    cudaFuncSetAttribute(mprep_kernel, cudaFuncAttributeMaxDynamicSharedMemorySize, SM_MP);
    cudaFuncSetAttribute(out_kernel,   cudaFuncAttributeMaxDynamicSharedMemorySize, SM_OUT);

    kv_kernel   <<<dim3(BHn, NSPLIT), 256, SM_KV >>>(key4, value4, wk_w4, wk_b);
    mprep_kernel<<<BHn,               256, SM_MP >>>(wv_w, wv_b, dense_w);
    out_kernel  <<<dim3(Sn / 64, Bn), 256, SM_OUT>>>(query4, wq_w4, wq_b, dense_b, out4);
}

// round 5
// speedup vs baseline: 8.2453x; 2.1757x over previous
#include <cuda_runtime.h>

// ---------------- problem constants ----------------
constexpr int Bn = 4;
constexpr int Sn = 4096;
constexpr int Hn = 16;
constexpr int BHn = 64;
constexpr int NSPLIT = 32;
constexpr int SCHUNK = Sn / NSPLIT;   // 128
constexpr int CH  = 64;               // s-rows per staged chunk
constexpr int NCH = SCHUNK / CH;      // 2
constexpr float PIC = 3.1415f;        // verbatim constant from reference

// ---------------- static device scratch ----------------
__device__ float    g_part  [NSPLIT * 64 * 8192];  // slot x bh x [128x64] fp32 partials
__device__ float    g_partKs[NSPLIT * 64 * 128];   // slot x bh x stacked ksum
__device__ unsigned g_Mst   [64 * 8192];           // bh x [128x64]  tf32 ([M;Mp] dense-folded)
__device__ float    g_Ks    [64 * 128];            // bh x stacked [Ksum;Kpsum] fp32

// ---------------- helpers ----------------
__device__ __forceinline__ unsigned tf32c(float f) {
    unsigned r; asm("cvt.rna.tf32.f32 %0,%1;" : "=r"(r) : "f"(f)); return r;
}
__device__ __forceinline__ void mma8(float* c,
    unsigned a0, unsigned a1, unsigned a2, unsigned a3, unsigned b0, unsigned b1)
{
    asm volatile(
        "mma.sync.aligned.m16n8k8.row.col.f32.tf32.tf32.f32 "
        "{%0,%1,%2,%3},{%4,%5,%6,%7},{%8,%9},{%0,%1,%2,%3};"
        : "+f"(c[0]), "+f"(c[1]), "+f"(c[2]), "+f"(c[3])
        : "r"(a0), "r"(a1), "r"(a2), "r"(a3), "r"(b0), "r"(b1));
}
__device__ __forceinline__ float elu1(float v) { return v > 0.f ? v + 1.f : __expf(v); }

// ===========================================================================
// Kernel 1 (tensor): per (bh, split):
//   Kp = elu1(rawK @ Wk_h + bk)           [mma tf32, M=64 N=64 K=64 per chunk]
//   C[128][64+ones] += [Kp;sin*Kp]^T @ V  [mma tf32, M=128 N=72 K=64 per chunk]
//   column 64 of the ones-extended V yields the stacked ksum for free.
// ===========================================================================
__global__ __launch_bounds__(256, 2)
void kv_kernel(const float4* __restrict__ key4, const float4* __restrict__ value4,
               const float4* __restrict__ wk_w4, const float* __restrict__ wk_b)
{
    extern __shared__ unsigned smu[];
    unsigned* sWk = smu;              // 64 x 72  (tf32 weights, [d][c])
    unsigned* sK  = sWk + 64 * 72;    // 64 x 68  (tf32 raw K,  [s][d])
    unsigned* sV  = sK  + 64 * 68;    // 64 x 72  (tf32 V + ones col, [s][z])
    unsigned* sA  = sV  + 64 * 72;    // 64 x 136 (tf32 stacked kp, [s][x 0..127])
    float* sSin  = (float*)(sA + 64 * 136);  // 64
    float* sBias = sSin + 64;                // 64

    const int bh = blockIdx.x, split = blockIdx.y;
    const int b  = bh >> 4,   h     = bh & 15;
    const int tid = threadIdx.x;
    const int lane = tid & 31, wid = tid >> 5;
    const int g = lane >> 2, tig = lane & 3;
    const int sbase = split * SCHUNK;

    // stage Wk (tf32) + bias
    #pragma unroll
    for (int t = 0; t < 4; t++) {
        int idx = tid + t * 256; int d = idx >> 4, c4 = idx & 15;
        float4 w = wk_w4[d * 256 + h * 16 + c4];
        uint4 u = make_uint4(tf32c(w.x), tf32c(w.y), tf32c(w.z), tf32c(w.w));
        *(uint4*)&sWk[d * 72 + c4 * 4] = u;
    }
    if (tid < 64) {
        sBias[tid] = wk_b[h * 64 + tid];
        #pragma unroll
        for (int j = 0; j < 8; j++)
            sV[tid * 72 + 64 + j] = (j == 0) ? 0x3F800000u : 0u;  // ones column
    }

    // stage chunk 0
    #pragma unroll
    for (int t = 0; t < 4; t++) {
        int idx = tid + t * 256; int r = idx >> 4, c4 = idx & 15;
        size_t gi = ((size_t)(b * Sn + sbase + r)) * 16 + c4;
        float4 k = key4[gi], v = value4[gi];
        *(uint4*)&sK[r * 68 + c4 * 4] = make_uint4(tf32c(k.x), tf32c(k.y), tf32c(k.z), tf32c(k.w));
        *(uint4*)&sV[r * 72 + c4 * 4] = make_uint4(tf32c(v.x), tf32c(v.y), tf32c(v.z), tf32c(v.w));
    }
    if (tid < 64) sSin[tid] = sinf(PIC * (float)(sbase + tid) / (float)Sn);
    __syncthreads();

    const int m0p = (wid & 3) * 16;      // proj rows
    const int n0p = (wid >> 2) * 32;     // proj cols
    const int x0  = wid * 16;            // accum stacked rows

    float acc[9][4];
    #pragma unroll
    for (int nt = 0; nt < 9; nt++)
        #pragma unroll
        for (int j = 0; j < 4; j++) acc[nt][j] = 0.f;

    for (int cc = 0; cc < NCH; cc++) {
        // ---- projection mma: pc = rawK @ Wk + bias ----
        float pc[4][4];
        #pragma unroll
        for (int nt = 0; nt < 4; nt++) {
            int col0 = n0p + 8 * nt + 2 * tig;
            pc[nt][0] = sBias[col0]; pc[nt][1] = sBias[col0 + 1];
            pc[nt][2] = sBias[col0]; pc[nt][3] = sBias[col0 + 1];
        }
        #pragma unroll
        for (int ks = 0; ks < 8; ks++) {
            int k0 = ks * 8;
            unsigned a0 = sK[(m0p + g)     * 68 + k0 + tig];
            unsigned a1 = sK[(m0p + g + 8) * 68 + k0 + tig];
            unsigned a2 = sK[(m0p + g)     * 68 + k0 + tig + 4];
            unsigned a3 = sK[(m0p + g + 8) * 68 + k0 + tig + 4];
            #pragma unroll
            for (int nt = 0; nt < 4; nt++) {
                int n = n0p + 8 * nt + g;
                unsigned b0 = sWk[(k0 + tig)     * 72 + n];
                unsigned b1 = sWk[(k0 + tig + 4) * 72 + n];
                mma8(pc[nt], a0, a1, a2, a3, b0, b1);
            }
        }
        // ---- elu + store stacked [kp | sin*kp] ----
        {
            float s1 = sSin[m0p + g], s2 = sSin[m0p + g + 8];
            int r1 = (m0p + g) * 136, r2 = (m0p + g + 8) * 136;
            #pragma unroll
            for (int nt = 0; nt < 4; nt++) {
                int col0 = n0p + 8 * nt + 2 * tig;
                float v00 = elu1(pc[nt][0]), v01 = elu1(pc[nt][1]);
                float v10 = elu1(pc[nt][2]), v11 = elu1(pc[nt][3]);
                sA[r1 + col0]          = tf32c(v00);
                sA[r1 + col0 + 1]      = tf32c(v01);
                sA[r2 + col0]          = tf32c(v10);
                sA[r2 + col0 + 1]      = tf32c(v11);
                sA[r1 + 64 + col0]     = tf32c(v00 * s1);
                sA[r1 + 64 + col0 + 1] = tf32c(v01 * s1);
                sA[r2 + 64 + col0]     = tf32c(v10 * s2);
                sA[r2 + 64 + col0 + 1] = tf32c(v11 * s2);
            }
        }
        __syncthreads();

        // ---- accumulation mma: C += A_stk^T-form @ V (ones-extended) ----
        #pragma unroll
        for (int ks = 0; ks < 8; ks++) {
            int k0 = ks * 8;
            unsigned a0 = sA[(k0 + tig)     * 136 + x0 + g];
            unsigned a1 = sA[(k0 + tig)     * 136 + x0 + g + 8];
            unsigned a2 = sA[(k0 + tig + 4) * 136 + x0 + g];
            unsigned a3 = sA[(k0 + tig + 4) * 136 + x0 + g + 8];
            #pragma unroll
            for (int nt = 0; nt < 9; nt++) {
                int n = 8 * nt + g;
                unsigned b0 = sV[(k0 + tig)     * 72 + n];
                unsigned b1 = sV[(k0 + tig + 4) * 72 + n];
                mma8(acc[nt], a0, a1, a2, a3, b0, b1);
            }
        }
        __syncthreads();

        if (cc + 1 < NCH) {
            #pragma unroll
            for (int t = 0; t < 4; t++) {
                int idx = tid + t * 256; int r = idx >> 4, c4 = idx & 15;
                size_t gi = ((size_t)(b * Sn + sbase + (cc + 1) * CH + r)) * 16 + c4;
                float4 k = key4[gi], v = value4[gi];
                *(uint4*)&sK[r * 68 + c4 * 4] = make_uint4(tf32c(k.x), tf32c(k.y), tf32c(k.z), tf32c(k.w));
                *(uint4*)&sV[r * 72 + c4 * 4] = make_uint4(tf32c(v.x), tf32c(v.y), tf32c(v.z), tf32c(v.w));
            }
            if (tid < 64)
                sSin[tid] = sinf(PIC * (float)(sbase + (cc + 1) * CH + tid) / (float)Sn);
            __syncthreads();
        }
    }

    // ---- write fp32 partials ----
    {
        size_t base = ((size_t)(split * 64 + bh)) * 8192;
        #pragma unroll
        for (int nt = 0; nt < 8; nt++) {
            int col0 = 8 * nt + 2 * tig;
            g_part[base + (size_t)(x0 + g)     * 64 + col0]     = acc[nt][0];
            g_part[base + (size_t)(x0 + g)     * 64 + col0 + 1] = acc[nt][1];
            g_part[base + (size_t)(x0 + g + 8) * 64 + col0]     = acc[nt][2];
            g_part[base + (size_t)(x0 + g + 8) * 64 + col0 + 1] = acc[nt][3];
        }
        if (tig == 0) {
            g_partKs[(split * 64 + bh) * 128 + x0 + g]     = acc[8][0];
            g_partKs[(split * 64 + bh) * 128 + x0 + g + 8] = acc[8][2];
        }
    }
}

// ===========================================================================
// Kernel 2: per bh — reduce partials, fold V-proj + dense (fp32 SIMT):
//   G = Wv_h @ Wd_h ; bvd = bv_h @ Wd_h
//   [M;Mp] = Craw @ G + [Ksum;Kpsum] (outer) bvd  -> tf32 ; Ksum fp32.
// ===========================================================================
constexpr int PAD = 68;
__global__ __launch_bounds__(256)
void mprep_kernel(const float* __restrict__ wv_w, const float* __restrict__ wv_b,
                  const float* __restrict__ dense_w)
{
    extern __shared__ float sm[];
    float* sC    = sm;                   // 128*68
    float* sWv   = sC   + 128 * PAD;     // 64*68
    float* sWd   = sWv  + 64 * PAD;      // 64*68
    float* sG    = sWd  + 64 * PAD;      // 64*68
    float* sKsum = sG   + 64 * PAD;      // 128
    float* sBvd  = sKsum + 128;          // 64
    float4* sC4 = (float4*)sC;
    const float4* g_part4 = (const float4*)g_part;

    const int bh = blockIdx.x, h = bh & 15, tid = threadIdx.x;

    #pragma unroll
    for (int t = 0; t < 16; t++) {
        int i = tid + t * 256; int k = i >> 6, c = i & 63;
        sWv[k * PAD + c] = wv_w[k * 1024 + h * 64 + c];
        sWd[k * PAD + c] = dense_w[(h * 64 + k) * 64 + c];
    }
    #pragma unroll
    for (int t = 0; t < 8; t++) {
        int idx = tid + t * 256; int r = idx >> 4, c4 = idx & 15;
        float4 s = make_float4(0.f, 0.f, 0.f, 0.f);
        for (int sl = 0; sl < NSPLIT; sl++) {
            float4 v = g_part4[((size_t)(sl * 64 + bh)) * 2048 + idx];
            s.x += v.x; s.y += v.y; s.z += v.z; s.w += v.w;
        }
        sC4[r * 17 + c4] = s;
    }
    if (tid < 128) {
        float s = 0.f;
        for (int sl = 0; sl < NSPLIT; sl++) s += g_partKs[(sl * 64 + bh) * 128 + tid];
        sKsum[tid] = s;
        g_Ks[bh * 128 + tid] = s;
    }
    __syncthreads();

    const int r  = tid >> 2;
    const int c0 = (tid & 3) * 16;

    // G = Wv @ Wd
    {
        float a16[16];
        #pragma unroll
        for (int j = 0; j < 16; j++) a16[j] = 0.f;
        for (int kk = 0; kk < 64; kk++) {
            float a = sWv[r * PAD + kk];
            #pragma unroll
            for (int j = 0; j < 16; j++) a16[j] += a * sWd[kk * PAD + c0 + j];
        }
        #pragma unroll
        for (int j = 0; j < 16; j++) sG[r * PAD + c0 + j] = a16[j];
    }
    if (tid < 64) {
        float s = 0.f;
        for (int c = 0; c < 64; c++) s += wv_b[h * 64 + c] * sWd[c * PAD + tid];
        sBvd[tid] = s;
    }
    __syncthreads();

    // [M;Mp] = sC @ sG + ksum (outer) bvd   -> tf32
    {
        float m0[16], m1[16];
        #pragma unroll
        for (int j = 0; j < 16; j++) { m0[j] = 0.f; m1[j] = 0.f; }
        for (int kk = 0; kk < 64; kk++) {
            float a0 = sC[r * PAD + kk];
            float a1 = sC[(r + 64) * PAD + kk];
            #pragma unroll
            for (int j = 0; j < 16; j++) {
                float gv = sG[kk * PAD + c0 + j];
                m0[j] += a0 * gv; m1[j] += a1 * gv;
            }
        }
        float k0 = sKsum[r], k1 = sKsum[r + 64];
        #pragma unroll
        for (int j = 0; j < 16; j++) {
            m0[j] += k0 * sBvd[c0 + j];
            m1[j] += k1 * sBvd[c0 + j];
        }
        int ob0 = bh * 8192 + r * 64 + c0;
        int ob1 = bh * 8192 + (r + 64) * 64 + c0;
        #pragma unroll
        for (int j = 0; j < 16; j++) {
            g_Mst[ob0 + j] = tf32c(m0[j]);
            g_Mst[ob1 + j] = tf32c(m1[j]);
        }
    }
}

// ===========================================================================
// Kernel 3 (tensor): per (b, 64-row s-tile), loop heads:
//   q = elu1(rawQ @ Wq_h + bq)   [mma]
//   den = 1/(q.Ks + w*(q.Kps) + 1e-5)
//   accO += den * ([q | w*q] @ [M_h;Mp_h])   [mma, K=128]
// ===========================================================================
__global__ __launch_bounds__(256, 2)
void out_kernel(const float4* __restrict__ query4,
                const float4* __restrict__ wq_w4, const float* __restrict__ wq_b,
                const float* __restrict__ dense_b, float* __restrict__ out)
{
    extern __shared__ unsigned smu[];
    unsigned* sQraw = smu;                  // 64 x 68  tf32 raw Q
    unsigned* sWq   = sQraw + 64 * 68;      // 64 x 72  tf32 Wq head slice
    unsigned* sB    = sWq   + 64 * 72;      // 128 x 72 tf32 [M;Mp]
    unsigned* sQ    = sB    + 128 * 72;     // 64 x 132 tf32 [q | w*q]
    float* sKs  = (float*)(sQ + 64 * 132);  // 128
    float* sWs  = sKs + 128;                // 64
    float* sQb  = sWs + 64;                 // 64
    float* sDot = sQb + 64;                 // 64 x 4 (d0h0,d0h1,d1h0,d1h1)

    const int b  = blockIdx.y;
    const int s0 = blockIdx.x * 64;
    const int tid = threadIdx.x;
    const int lane = tid & 31, wid = tid >> 5;
    const int g = lane >> 2, tig = lane & 3;
    const int mt = wid & 3, nh = wid >> 2;
    const int m0 = mt * 16, n0 = nh * 32;

    // stage raw Q (tf32) + pos weights
    #pragma unroll
    for (int t = 0; t < 4; t++) {
        int idx = tid + t * 256; int r = idx >> 4, c4 = idx & 15;
        float4 q = query4[((size_t)(b * Sn + s0 + r)) * 16 + c4];
        *(uint4*)&sQraw[r * 68 + c4 * 4] = make_uint4(tf32c(q.x), tf32c(q.y), tf32c(q.z), tf32c(q.w));
    }
    if (tid < 64) {
        float ps = PIC * (float)(s0 + tid) / (float)Sn;
        sWs[tid] = cosf(ps) + sinf(ps);
    }

    float accO[4][4];
    #pragma unroll
    for (int nt = 0; nt < 4; nt++)
        #pragma unroll
        for (int j = 0; j < 4; j++) accO[nt][j] = 0.f;
    __syncthreads();

    const uint4* g_Mst4 = (const uint4*)g_Mst;

    for (int h = 0; h < Hn; h++) {
        const int bh = b * 16 + h;
        // ---- stage head data ----
        #pragma unroll
        for (int t = 0; t < 4; t++) {
            int idx = tid + t * 256; int d = idx >> 4, c4 = idx & 15;
            float4 w = wq_w4[d * 256 + h * 16 + c4];
            *(uint4*)&sWq[d * 72 + c4 * 4] = make_uint4(tf32c(w.x), tf32c(w.y), tf32c(w.z), tf32c(w.w));
        }
        #pragma unroll
        for (int t = 0; t < 8; t++) {                 // FIX: full 2048 uint4 per bh
            int idx = tid + t * 256; int r = idx >> 4, c4 = idx & 15;
            *(uint4*)&sB[r * 72 + c4 * 4] = g_Mst4[(size_t)bh * 2048 + idx];
        }
        if (tid < 128)      sKs[tid] = g_Ks[bh * 128 + tid];
        else if (tid < 192) sQb[tid - 128] = wq_b[h * 64 + (tid - 128)];
        __syncthreads();

        // ---- q projection mma ----
        float pc[4][4];
        #pragma unroll
        for (int nt = 0; nt < 4; nt++) {
            int col0 = n0 + 8 * nt + 2 * tig;
            pc[nt][0] = sQb[col0]; pc[nt][1] = sQb[col0 + 1];
            pc[nt][2] = sQb[col0]; pc[nt][3] = sQb[col0 + 1];
        }
        #pragma unroll
        for (int ks = 0; ks < 8; ks++) {
            int k0 = ks * 8;
            unsigned a0 = sQraw[(m0 + g)     * 68 + k0 + tig];
            unsigned a1 = sQraw[(m0 + g + 8) * 68 + k0 + tig];
            unsigned a2 = sQraw[(m0 + g)     * 68 + k0 + tig + 4];
            unsigned a3 = sQraw[(m0 + g + 8) * 68 + k0 + tig + 4];
            #pragma unroll
            for (int nt = 0; nt < 4; nt++) {
                int n = n0 + 8 * nt + g;
                unsigned b0 = sWq[(k0 + tig)     * 72 + n];
                unsigned b1 = sWq[(k0 + tig + 4) * 72 + n];
                mma8(pc[nt], a0, a1, a2, a3, b0, b1);
            }
        }

        // ---- elu, partial denominators, store [q | w*q] ----
        {
            float w1 = sWs[m0 + g], w2 = sWs[m0 + g + 8];
            int r1 = (m0 + g) * 132, r2 = (m0 + g + 8) * 132;
            float d0a = 0.f, d1a = 0.f, d0b = 0.f, d1b = 0.f;
            #pragma unroll
            for (int nt = 0; nt < 4; nt++) {
                int col0 = n0 + 8 * nt + 2 * tig;
                float ks0 = sKs[col0],      ks1 = sKs[col0 + 1];
                float kp0 = sKs[64 + col0], kp1 = sKs[64 + col0 + 1];
                float v00 = elu1(pc[nt][0]), v01 = elu1(pc[nt][1]);
                float v10 = elu1(pc[nt][2]), v11 = elu1(pc[nt][3]);
                d0a += v00 * ks0 + v01 * ks1;  d1a += v00 * kp0 + v01 * kp1;
                d0b += v10 * ks0 + v11 * ks1;  d1b += v10 * kp0 + v11 * kp1;
                sQ[r1 + col0]          = tf32c(v00);
                sQ[r1 + col0 + 1]      = tf32c(v01);
                sQ[r2 + col0]          = tf32c(v10);
                sQ[r2 + col0 + 1]      = tf32c(v11);
                sQ[r1 + 64 + col0]     = tf32c(v00 * w1);
                sQ[r1 + 64 + col0 + 1] = tf32c(v01 * w1);
                sQ[r2 + 64 + col0]     = tf32c(v10 * w2);
                sQ[r2 + 64 + col0 + 1] = tf32c(v11 * w2);
            }
            d0a += __shfl_xor_sync(0xffffffffu, d0a, 1); d0a += __shfl_xor_sync(0xffffffffu, d0a, 2);
            d1a += __shfl_xor_sync(0xffffffffu, d1a, 1); d1a += __shfl_xor_sync(0xffffffffu, d1a, 2);
            d0b += __shfl_xor_sync(0xffffffffu, d0b, 1); d0b += __shfl_xor_sync(0xffffffffu, d0b, 2);
            d1b += __shfl_xor_sync(0xffffffffu, d1b, 1); d1b += __shfl_xor_sync(0xffffffffu, d1b, 2);
            if (tig == 0) {
                sDot[(m0 + g) * 4 + nh]         = d0a;
                sDot[(m0 + g) * 4 + 2 + nh]     = d1a;
                sDot[(m0 + g + 8) * 4 + nh]     = d0b;
                sDot[(m0 + g + 8) * 4 + 2 + nh] = d1b;
            }
        }
        __syncthreads();

        // ---- denominators ----
        int r1 = m0 + g, r2 = m0 + g + 8;
        float den1 = 1.0f / (sDot[r1 * 4] + sDot[r1 * 4 + 1]
                     + sWs[r1] * (sDot[r1 * 4 + 2] + sDot[r1 * 4 + 3]) + 1e-5f);
        float den2 = 1.0f / (sDot[r2 * 4] + sDot[r2 * 4 + 1]
                     + sWs[r2] * (sDot[r2 * 4 + 2] + sDot[r2 * 4 + 3]) + 1e-5f);

        // ---- o-GEMM mma: K=128 ----
        float oc[4][4];
        #pragma unroll
        for (int nt = 0; nt < 4; nt++)
            #pragma unroll
            for (int j = 0; j < 4; j++) oc[nt][j] = 0.f;
        #pragma unroll
        for (int ks = 0; ks < 16; ks++) {
            int k0 = ks * 8;
            unsigned a0 = sQ[(m0 + g)     * 132 + k0 + tig];
            unsigned a1 = sQ[(m0 + g + 8) * 132 + k0 + tig];
            unsigned a2 = sQ[(m0 + g)     * 132 + k0 + tig + 4];
            unsigned a3 = sQ[(m0 + g + 8) * 132 + k0 + tig + 4];
            #pragma unroll
            for (int nt = 0; nt < 4; nt++) {
                int n = n0 + 8 * nt + g;
                unsigned b0 = sB[(k0 + tig)     * 72 + n];
                unsigned b1 = sB[(k0 + tig + 4) * 72 + n];
                mma8(oc[nt], a0, a1, a2, a3, b0, b1);
            }
        }
        #pragma unroll
        for (int nt = 0; nt < 4; nt++) {
            accO[nt][0] += den1 * oc[nt][0];
            accO[nt][1] += den1 * oc[nt][1];
            accO[nt][2] += den2 * oc[nt][2];
            accO[nt][3] += den2 * oc[nt][3];
        }
        __syncthreads();
    }

    // ---- epilogue: + dense_b ----
    #pragma unroll
    for (int nt = 0; nt < 4; nt++) {
        int col0 = n0 + 8 * nt + 2 * tig;
        float db0 = dense_b[col0], db1 = dense_b[col0 + 1];
        size_t o1 = ((size_t)(b * Sn + s0 + m0 + g)) * 64 + col0;
        size_t o2 = ((size_t)(b * Sn + s0 + m0 + g + 8)) * 64 + col0;
        out[o1]     = accO[nt][0] + db0;
        out[o1 + 1] = accO[nt][1] + db1;
        out[o2]     = accO[nt][2] + db0;
        out[o2 + 1] = accO[nt][3] + db1;
    }
}

// ---------------------------------------------------------------------------
extern "C" void kernel_launch(void* const* d_in, const int* in_sizes, int n_in,
                              void* d_out, int out_size)
{
    const float4* query4  = (const float4*)d_in[0];
    const float4* key4    = (const float4*)d_in[1];
    const float4* value4  = (const float4*)d_in[2];
    // d_in[3] = attn_mask (unused by the math)
    const float4* wq_w4   = (const float4*)d_in[4];
    const float*  wq_b    = (const float*)d_in[5];
    const float4* wk_w4   = (const float4*)d_in[6];
    const float*  wk_b    = (const float*)d_in[7];
    const float*  wv_w    = (const float*)d_in[8];
    const float*  wv_b    = (const float*)d_in[9];
    const float*  dense_w = (const float*)d_in[10];
    const float*  dense_b = (const float*)d_in[11];
    float* out = (float*)d_out;

    constexpr int SM_KV  = (64*72 + 64*68 + 64*72 + 64*136 + 128) * 4;          // 89.6 KB
    constexpr int SM_MP  = (128*PAD + 3*64*PAD + 128 + 64) * 4;                 // 87.8 KB
    constexpr int SM_OUT = (64*68 + 64*72 + 128*72 + 64*132 + 128+64+64+256)*4; // 108.5 KB

    cudaFuncSetAttribute(kv_kernel,    cudaFuncAttributeMaxDynamicSharedMemorySize, SM_KV);
    cudaFuncSetAttribute(mprep_kernel, cudaFuncAttributeMaxDynamicSharedMemorySize, SM_MP);
    cudaFuncSetAttribute(out_kernel,   cudaFuncAttributeMaxDynamicSharedMemorySize, SM_OUT);

    kv_kernel   <<<dim3(BHn, NSPLIT), 256, SM_KV >>>(key4, value4, wk_w4, wk_b);
    mprep_kernel<<<BHn,               256, SM_MP >>>(wv_w, wv_b, dense_w);
    out_kernel  <<<dim3(Sn / 64, Bn), 256, SM_OUT>>>(query4, wq_w4, wq_b, dense_b, out);
}